// round 13
// baseline (speedup 1.0000x reference)
#include <cuda_runtime.h>
#include <cstdint>

#define B_    96
#define NW    10
#define NTOK  144
#define CH    192
#define HEADS_ 6
#define DH    32
#define NQKV  576
#define MROWS (B_ * NW * NTOK)     // 138240

// dense GEMM tiling (bf16 split)
#define BM 128
#define BN 64
#define BK 32
#define KITERS (CH / BK)           // 6
#define SH 40                      // bf16 row stride (80 B, conflict-free)
#define STAGE_AH 0
#define STAGE_AL (BM * SH * 2)               // 10240
#define STAGE_BH (STAGE_AL + BM * SH * 2)    // 20480
#define STAGE_BL (STAGE_BH + BN * SH * 2)    // 25600
#define STAGE_BYTES (STAGE_BL + BN * SH * 2) // 30720
#define GEMM_SMEM_BYTES (3 * STAGE_BYTES)    // 92160

// attention smem (bf16 halves)
#define QKH 40
#define VTH 152
#define BY_QH 0
#define BY_QL (BY_QH + NTOK * QKH * 2)
#define BY_KH (BY_QL + NTOK * QKH * 2)
#define BY_KL (BY_KH + NTOK * QKH * 2)
#define BY_VH (BY_KL + NTOK * QKH * 2)
#define BY_VL (BY_VH + DH * VTH * 2)
#define ATTN_SMEM_BYTES (BY_VL + DH * VTH * 2)   // 65536

// Scratch
__device__ float    g_qkv[(size_t)3 * B_ * NW * HEADS_ * NTOK * DH];
__device__ float    g_bias[(size_t)NW * HEADS_ * NTOK * NTOK];
__device__ uint16_t g_xh[(size_t)MROWS * CH];
__device__ uint16_t g_xl[(size_t)MROWS * CH];
__device__ uint16_t g_oh[(size_t)MROWS * CH];
__device__ uint16_t g_ol[(size_t)MROWS * CH];
__device__ uint16_t g_wqh[NQKV * CH];
__device__ uint16_t g_wql[NQKV * CH];
__device__ uint16_t g_wph[CH * CH];
__device__ uint16_t g_wpl[CH * CH];

// ---------------------------------------------------------------------------
// helpers
// ---------------------------------------------------------------------------
__device__ __forceinline__ uint32_t smem_u32(const void* p) {
    uint32_t a;
    asm("{ .reg .u64 t; cvta.to.shared.u64 t, %1; cvt.u32.u64 %0, t; }"
        : "=r"(a) : "l"(p));
    return a;
}
__device__ __forceinline__ void ldmA(uint32_t a[4], uint32_t addr) {
    asm volatile("ldmatrix.sync.aligned.m8n8.x4.shared.b16 {%0,%1,%2,%3}, [%4];"
                 : "=r"(a[0]), "=r"(a[1]), "=r"(a[2]), "=r"(a[3]) : "r"(addr));
}
__device__ __forceinline__ void mma_bf16(float c[4], const uint32_t a[4],
                                         uint32_t b0, uint32_t b1) {
    asm volatile(
        "mma.sync.aligned.m16n8k16.row.col.f32.bf16.bf16.f32 "
        "{%0,%1,%2,%3},{%4,%5,%6,%7},{%8,%9},{%0,%1,%2,%3};"
        : "+f"(c[0]), "+f"(c[1]), "+f"(c[2]), "+f"(c[3])
        : "r"(a[0]), "r"(a[1]), "r"(a[2]), "r"(a[3]), "r"(b0), "r"(b1));
}
__device__ __forceinline__ uint16_t bf16rn(float x) {
    uint16_t r;
    asm("cvt.rn.bf16.f32 %0, %1;" : "=h"(r) : "f"(x));
    return r;
}
// pack (e0 -> low half, e1 -> high half); hi = truncated bf16 (exact split)
__device__ __forceinline__ uint32_t pack_hi(float e0, float e1) {
    return (__float_as_uint(e1) & 0xffff0000u) | (__float_as_uint(e0) >> 16);
}
__device__ __forceinline__ uint32_t pack_lo(float e0, float e1) {
    float h0 = __uint_as_float(__float_as_uint(e0) & 0xffff0000u);
    float h1 = __uint_as_float(__float_as_uint(e1) & 0xffff0000u);
    float l0 = e0 - h0, l1 = e1 - h1;
    uint32_t r;
    asm("cvt.rn.bf16x2.f32 %0, %1, %2;" : "=r"(r) : "f"(l1), "f"(l0));
    return r;
}
__device__ __forceinline__ void cp_async16(uint32_t dst, const void* src) {
    asm volatile("cp.async.cg.shared.global [%0], [%1], 16;" :: "r"(dst), "l"(src));
}
__device__ __forceinline__ void cp_commit() {
    asm volatile("cp.async.commit_group;");
}
template <int N>
__device__ __forceinline__ void cp_wait() {
    asm volatile("cp.async.wait_group %0;" :: "n"(N));
}

// ---------------------------------------------------------------------------
// Pre-pass: split x into bf16 hi/lo; split+transpose weights.
// ---------------------------------------------------------------------------
__global__ __launch_bounds__(256) void split_x_kernel(const float* __restrict__ x)
{
    size_t n2 = (size_t)MROWS * CH / 2;
    size_t stride = (size_t)gridDim.x * 256;
    for (size_t i = blockIdx.x * 256ull + threadIdx.x; i < n2; i += stride) {
        float2 v = ((const float2*)x)[i];
        ((uint32_t*)g_xh)[i] = pack_hi(v.x, v.y);
        ((uint32_t*)g_xl)[i] = pack_lo(v.x, v.y);
    }
}

__global__ __launch_bounds__(192) void split_w_kernel(
    const float* __restrict__ wq, const float* __restrict__ wp)
{
    int n = blockIdx.x;            // 0..575: qkv, 576..767: proj
    int k = threadIdx.x;           // 0..191
    if (n < NQKV) {
        float v = wq[(size_t)k * NQKV + n];
        uint32_t hb = __float_as_uint(v) & 0xffff0000u;
        g_wqh[n * CH + k] = (uint16_t)(hb >> 16);
        g_wql[n * CH + k] = bf16rn(v - __uint_as_float(hb));
    } else {
        int n2 = n - NQKV;
        float v = wp[(size_t)k * CH + n2];
        uint32_t hb = __float_as_uint(v) & 0xffff0000u;
        g_wph[n2 * CH + k] = (uint16_t)(hb >> 16);
        g_wpl[n2 * CH + k] = bf16rn(v - __uint_as_float(hb));
    }
}

__global__ __launch_bounds__(256) void bias_precompute_kernel(
    const float* __restrict__ bias_table, const int* __restrict__ pidx)
{
    int wh = blockIdx.x;
    int w = wh / HEADS_, h = wh % HEADS_;
    float* dst = g_bias + (size_t)wh * (NTOK * NTOK);
    for (int idx = threadIdx.x; idx < NTOK * NTOK; idx += 256) {
        int p = pidx[idx];
        dst[idx] = bias_table[(p * NW + w) * HEADS_ + h];
    }
}

// ---------------------------------------------------------------------------
// bf16 3-term split GEMM mainloop, cp.async 3-stage pipeline.
// A hi/lo: [M][192] bf16 row-major. B hi/lo: [N][192] bf16 (pre-transposed).
// 256 threads, 8 warps (4x2), 32x32 warp tiles. Pure ldmatrix + mma mainloop.
// Fragment address patterns identical to the (validated) attention kernel.
// ---------------------------------------------------------------------------
__device__ __forceinline__ void gemm_bf16_pipe(
    const uint16_t* __restrict__ Ah, const uint16_t* __restrict__ Al,
    const uint16_t* __restrict__ Bh, const uint16_t* __restrict__ Bl,
    int row0, int col0, char* smem, float acc[2][4][4])
{
    int tid  = threadIdx.x;
    int warp = tid >> 5, lane = tid & 31;
    int wr = warp >> 1, wc = warp & 1;
    int nbase = wc * 32;

    uint32_t sb = smem_u32(smem);
    int fr = tid >> 2, fc = tid & 3;          // fill coords: 64 rows x 4 chunks

    auto issue = [&](int s) {
        uint32_t st = sb + (uint32_t)((s % 3) * STAGE_BYTES);
        int k0 = s * BK;
#pragma unroll
        for (int l = 0; l < 2; l++) {
            int rr = fr + l * 64;
            size_t src = (size_t)(row0 + rr) * CH + k0 + fc * 8;
            cp_async16(st + STAGE_AH + rr * 80 + fc * 16, Ah + src);
            cp_async16(st + STAGE_AL + rr * 80 + fc * 16, Al + src);
        }
        {
            size_t src = (size_t)(col0 + fr) * CH + k0 + fc * 8;
            cp_async16(st + STAGE_BH + fr * 80 + fc * 16, Bh + src);
            cp_async16(st + STAGE_BL + fr * 80 + fc * 16, Bl + src);
        }
        cp_commit();
    };

    issue(0);
    issue(1);

    // ldmatrix offsets within a stage (attention-kernel patterns, stride 80 B)
    uint32_t aoff0 = STAGE_AH + (uint32_t)((wr * 32 + (lane & 15)) * 80) + (lane >> 4) * 16;
    uint32_t aoff1 = aoff0 + 16 * 80;
    uint32_t brw   = (uint32_t)((nbase + (lane & 7) + ((lane >> 4) << 3)) * 80)
                   + ((lane >> 3) & 1) * 16;
    uint32_t bhoff0 = STAGE_BH + brw;
    uint32_t bhoff1 = bhoff0 + 16 * 80;

    for (int i = 0; i < KITERS; i++) {
        cp_wait<1>();
        __syncthreads();
        if (i + 2 < KITERS) issue(i + 2);

        uint32_t st = sb + (uint32_t)((i % 3) * STAGE_BYTES);
#pragma unroll
        for (int c16 = 0; c16 < 2; c16++) {
            uint32_t kb = 32u * c16;
            uint32_t ah0[4], ah1[4], al0[4], al1[4];
            ldmA(ah0, st + aoff0 + kb);
            ldmA(ah1, st + aoff1 + kb);
            ldmA(al0, st + aoff0 + (STAGE_AL - STAGE_AH) + kb);
            ldmA(al1, st + aoff1 + (STAGE_AL - STAGE_AH) + kb);
            uint32_t bh0[4], bl0[4], bh1[4], bl1[4];
            ldmA(bh0, st + bhoff0 + kb);
            ldmA(bl0, st + bhoff0 + (STAGE_BL - STAGE_BH) + kb);
            ldmA(bh1, st + bhoff1 + kb);
            ldmA(bl1, st + bhoff1 + (STAGE_BL - STAGE_BH) + kb);

            // n-tile 0 (pair0 regs 0,1)
            mma_bf16(acc[0][0], ah0, bh0[0], bh0[1]);
            mma_bf16(acc[0][0], ah0, bl0[0], bl0[1]);
            mma_bf16(acc[0][0], al0, bh0[0], bh0[1]);
            mma_bf16(acc[1][0], ah1, bh0[0], bh0[1]);
            mma_bf16(acc[1][0], ah1, bl0[0], bl0[1]);
            mma_bf16(acc[1][0], al1, bh0[0], bh0[1]);
            // n-tile 1 (pair0 regs 2,3)
            mma_bf16(acc[0][1], ah0, bh0[2], bh0[3]);
            mma_bf16(acc[0][1], ah0, bl0[2], bl0[3]);
            mma_bf16(acc[0][1], al0, bh0[2], bh0[3]);
            mma_bf16(acc[1][1], ah1, bh0[2], bh0[3]);
            mma_bf16(acc[1][1], ah1, bl0[2], bl0[3]);
            mma_bf16(acc[1][1], al1, bh0[2], bh0[3]);
            // n-tile 2 (pair1 regs 0,1)
            mma_bf16(acc[0][2], ah0, bh1[0], bh1[1]);
            mma_bf16(acc[0][2], ah0, bl1[0], bl1[1]);
            mma_bf16(acc[0][2], al0, bh1[0], bh1[1]);
            mma_bf16(acc[1][2], ah1, bh1[0], bh1[1]);
            mma_bf16(acc[1][2], ah1, bl1[0], bl1[1]);
            mma_bf16(acc[1][2], al1, bh1[0], bh1[1]);
            // n-tile 3 (pair1 regs 2,3)
            mma_bf16(acc[0][3], ah0, bh1[2], bh1[3]);
            mma_bf16(acc[0][3], ah0, bl1[2], bl1[3]);
            mma_bf16(acc[0][3], al0, bh1[2], bh1[3]);
            mma_bf16(acc[1][3], ah1, bh1[2], bh1[3]);
            mma_bf16(acc[1][3], ah1, bl1[2], bl1[3]);
            mma_bf16(acc[1][3], al1, bh1[2], bh1[3]);
        }
    }
}

// ---------------------------------------------------------------------------
// GEMM1: qkv = x @ w_qkv + b_qkv, scatter into g_qkv [3,B,nW,H,N,Dh]
// ---------------------------------------------------------------------------
__global__ __launch_bounds__(256) void qkv_gemm_mma(const float* __restrict__ bias)
{
    extern __shared__ char gsm[];
    int row0 = blockIdx.y * BM;
    int col0 = blockIdx.x * BN;

    float acc[2][4][4];
#pragma unroll
    for (int m = 0; m < 2; m++)
#pragma unroll
        for (int n = 0; n < 4; n++)
#pragma unroll
            for (int j = 0; j < 4; j++) acc[m][n][j] = 0.f;

    gemm_bf16_pipe(g_xh, g_xl, g_wqh, g_wql, row0, col0, gsm, acc);

    int tid = threadIdx.x;
    int warp = tid >> 5, lane = tid & 31;
    int wr = warp >> 1, wc = warp & 1;
    int g = lane >> 2, la3 = lane & 3;

#pragma unroll
    for (int mr = 0; mr < 2; mr++) {
#pragma unroll
        for (int nr = 0; nr < 4; nr++) {
#pragma unroll
            for (int j = 0; j < 4; j++) {
                int row = row0 + wr * 32 + mr * 16 + g + ((j >> 1) << 3);
                int n   = col0 + wc * 32 + nr * 8 + la3 * 2 + (j & 1);
                float v = acc[mr][nr][j] + bias[n];
                int bw = row / NTOK, rr = row - bw * NTOK;
                int t = n / CH, rem = n - t * CH;
                int h = rem >> 5, d = rem & 31;
                g_qkv[((((size_t)t * (B_ * NW) + bw) * HEADS_ + h) * NTOK + rr) * DH + d] = v;
            }
        }
    }
}

// ---------------------------------------------------------------------------
// GEMM2: out = O @ w_proj + b_proj  (O pre-split bf16 by attention)
// ---------------------------------------------------------------------------
__global__ __launch_bounds__(256) void proj_gemm_mma(
    const float* __restrict__ bias, float* __restrict__ out)
{
    extern __shared__ char gsm[];
    int row0 = blockIdx.y * BM;
    int col0 = blockIdx.x * BN;

    float acc[2][4][4];
#pragma unroll
    for (int m = 0; m < 2; m++)
#pragma unroll
        for (int n = 0; n < 4; n++)
#pragma unroll
            for (int j = 0; j < 4; j++) acc[m][n][j] = 0.f;

    gemm_bf16_pipe(g_oh, g_ol, g_wph, g_wpl, row0, col0, gsm, acc);

    int tid = threadIdx.x;
    int warp = tid >> 5, lane = tid & 31;
    int wr = warp >> 1, wc = warp & 1;
    int g = lane >> 2, la3 = lane & 3;

#pragma unroll
    for (int mr = 0; mr < 2; mr++) {
#pragma unroll
        for (int nr = 0; nr < 4; nr++) {
#pragma unroll
            for (int j = 0; j < 4; j++) {
                int row = row0 + wr * 32 + mr * 16 + g + ((j >> 1) << 3);
                int n   = col0 + wc * 32 + nr * 8 + la3 * 2 + (j & 1);
                out[(size_t)row * CH + n] = acc[mr][nr][j] + bias[n];
            }
        }
    }
}

// ---------------------------------------------------------------------------
// Attention (R6 structure): one CTA per (b,w,h), 9 warps, 2 CTAs/SM.
// O written as bf16 hi/lo pair (consumed directly by proj GEMM).
// ---------------------------------------------------------------------------
__global__ __launch_bounds__(288, 2) void attn_mma_kernel(
    const float* __restrict__ mask)
{
    extern __shared__ char smc[];
    uint16_t* qh = (uint16_t*)(smc + BY_QH);
    uint16_t* ql = (uint16_t*)(smc + BY_QL);
    uint16_t* kh = (uint16_t*)(smc + BY_KH);
    uint16_t* kl = (uint16_t*)(smc + BY_KL);
    uint16_t* vh = (uint16_t*)(smc + BY_VH);
    uint16_t* vl = (uint16_t*)(smc + BY_VL);

    int tid = threadIdx.x;
    int h = blockIdx.x, w = blockIdx.y, b = blockIdx.z;

    size_t base = (((size_t)b * NW + w) * HEADS_ + h) * (NTOK * DH);
    const size_t seg = (size_t)(B_ * NW * HEADS_) * (NTOK * DH);
    const float* gq = g_qkv + base;
    const float* gk = gq + seg;
    const float* gv = gk + seg;

    for (int idx = tid; idx < NTOK * DH; idx += 288) {
        int r = idx >> 5, c = idx & 31;
        float x = gq[idx];
        uint32_t xb = __float_as_uint(x) & 0xffff0000u;
        qh[r * QKH + c] = (uint16_t)(xb >> 16);
        ql[r * QKH + c] = bf16rn(x - __uint_as_float(xb));
        float y = gk[idx];
        uint32_t yb = __float_as_uint(y) & 0xffff0000u;
        kh[r * QKH + c] = (uint16_t)(yb >> 16);
        kl[r * QKH + c] = bf16rn(y - __uint_as_float(yb));
        float z = gv[idx];
        uint32_t zb = __float_as_uint(z) & 0xffff0000u;
        vh[c * VTH + r] = (uint16_t)(zb >> 16);
        vl[c * VTH + r] = bf16rn(z - __uint_as_float(zb));
    }
    __syncthreads();

    int warp = tid >> 5, lane = tid & 31;
    int r0 = warp * 16;
    int g = lane >> 2, la3 = lane & 3;

    float acc[18][4];
#pragma unroll
    for (int t = 0; t < 18; t++)
#pragma unroll
        for (int j = 0; j < 4; j++) acc[t][j] = 0.f;

    uint32_t aQh = smem_u32(qh) + (uint32_t)(r0 + (lane & 15)) * (QKH * 2) + (lane >> 4) * 16;
    uint32_t aQl = smem_u32(ql) + (uint32_t)(r0 + (lane & 15)) * (QKH * 2) + (lane >> 4) * 16;
    uint32_t brw = (uint32_t)((lane & 7) + ((lane >> 4) << 3)) * (QKH * 2) + ((lane >> 3) & 1) * 16;
    uint32_t bKh = smem_u32(kh) + brw;
    uint32_t bKl = smem_u32(kl) + brw;

#pragma unroll
    for (int c = 0; c < 2; c++) {
        uint32_t ah[4], al[4];
        ldmA(ah, aQh + 32 * c);
        ldmA(al, aQl + 32 * c);
#pragma unroll
        for (int p = 0; p < 9; p++) {
            uint32_t bh4[4], bl4[4];
            uint32_t off = (uint32_t)(p * 16 * QKH * 2) + 32 * c;
            ldmA(bh4, bKh + off);
            ldmA(bl4, bKl + off);
            mma_bf16(acc[2 * p],     ah, bh4[0], bh4[1]);
            mma_bf16(acc[2 * p],     ah, bl4[0], bl4[1]);
            mma_bf16(acc[2 * p],     al, bh4[0], bh4[1]);
            mma_bf16(acc[2 * p + 1], ah, bh4[2], bh4[3]);
            mma_bf16(acc[2 * p + 1], ah, bl4[2], bl4[3]);
            mma_bf16(acc[2 * p + 1], al, bh4[2], bh4[3]);
        }
    }

    const float scale = 0.17677669529663687f;
    const float* biasW = g_bias + (size_t)(w * HEADS_ + h) * (NTOK * NTOK);
    const float* maskB = mask + (size_t)b * NTOK * NTOK;
    const float* bA = biasW + (r0 + g) * NTOK;
    const float* mA = maskB + (r0 + g) * NTOK;
    const float* bB = bA + 8 * NTOK;
    const float* mB = mA + 8 * NTOK;

    float mx0 = -3.4e38f, mx1 = -3.4e38f;
#pragma unroll
    for (int t = 0; t < 18; t++) {
        int col = t * 8 + 2 * la3;
        float2 bb = *(const float2*)(bA + col);
        float2 mm = *(const float2*)(mA + col);
        float2 bb2 = *(const float2*)(bB + col);
        float2 mm2 = *(const float2*)(mB + col);
        acc[t][0] = fmaf(acc[t][0], scale, bb.x + mm.x);
        acc[t][1] = fmaf(acc[t][1], scale, bb.y + mm.y);
        acc[t][2] = fmaf(acc[t][2], scale, bb2.x + mm2.x);
        acc[t][3] = fmaf(acc[t][3], scale, bb2.y + mm2.y);
        mx0 = fmaxf(mx0, fmaxf(acc[t][0], acc[t][1]));
        mx1 = fmaxf(mx1, fmaxf(acc[t][2], acc[t][3]));
    }
    mx0 = fmaxf(mx0, __shfl_xor_sync(0xffffffffu, mx0, 1));
    mx0 = fmaxf(mx0, __shfl_xor_sync(0xffffffffu, mx0, 2));
    mx1 = fmaxf(mx1, __shfl_xor_sync(0xffffffffu, mx1, 1));
    mx1 = fmaxf(mx1, __shfl_xor_sync(0xffffffffu, mx1, 2));

    float s0 = 0.f, s1 = 0.f;
#pragma unroll
    for (int t = 0; t < 18; t++) {
        acc[t][0] = __expf(acc[t][0] - mx0);
        acc[t][1] = __expf(acc[t][1] - mx0);
        acc[t][2] = __expf(acc[t][2] - mx1);
        acc[t][3] = __expf(acc[t][3] - mx1);
        s0 += acc[t][0] + acc[t][1];
        s1 += acc[t][2] + acc[t][3];
    }
    s0 += __shfl_xor_sync(0xffffffffu, s0, 1);
    s0 += __shfl_xor_sync(0xffffffffu, s0, 2);
    s1 += __shfl_xor_sync(0xffffffffu, s1, 1);
    s1 += __shfl_xor_sync(0xffffffffu, s1, 2);
    float inv0 = 1.f / s0;
    float inv1 = 1.f / s1;

    float o[4][4];
#pragma unroll
    for (int t = 0; t < 4; t++)
#pragma unroll
        for (int j = 0; j < 4; j++) o[t][j] = 0.f;

    uint32_t vrw = (uint32_t)((lane & 7) + ((lane >> 4) << 3)) * (VTH * 2) + ((lane >> 3) & 1) * 16;
    uint32_t bV0h = smem_u32(vh) + vrw;
    uint32_t bV0l = smem_u32(vl) + vrw;
    uint32_t bV1h = bV0h + 16 * VTH * 2;
    uint32_t bV1l = bV0l + 16 * VTH * 2;

#pragma unroll
    for (int c = 0; c < 9; c++) {
        uint32_t ah[4], al[4];
        ah[0] = pack_hi(acc[2 * c][0], acc[2 * c][1]);
        ah[1] = pack_hi(acc[2 * c][2], acc[2 * c][3]);
        ah[2] = pack_hi(acc[2 * c + 1][0], acc[2 * c + 1][1]);
        ah[3] = pack_hi(acc[2 * c + 1][2], acc[2 * c + 1][3]);
        al[0] = pack_lo(acc[2 * c][0], acc[2 * c][1]);
        al[1] = pack_lo(acc[2 * c][2], acc[2 * c][3]);
        al[2] = pack_lo(acc[2 * c + 1][0], acc[2 * c + 1][1]);
        al[3] = pack_lo(acc[2 * c + 1][2], acc[2 * c + 1][3]);

        uint32_t off = 32u * c;
        uint32_t v0h[4], v0l[4], v1h[4], v1l[4];
        ldmA(v0h, bV0h + off);
        ldmA(v0l, bV0l + off);
        ldmA(v1h, bV1h + off);
        ldmA(v1l, bV1l + off);

        mma_bf16(o[0], ah, v0h[0], v0h[1]);
        mma_bf16(o[0], ah, v0l[0], v0l[1]);
        mma_bf16(o[0], al, v0h[0], v0h[1]);
        mma_bf16(o[1], ah, v0h[2], v0h[3]);
        mma_bf16(o[1], ah, v0l[2], v0l[3]);
        mma_bf16(o[1], al, v0h[2], v0h[3]);
        mma_bf16(o[2], ah, v1h[0], v1h[1]);
        mma_bf16(o[2], ah, v1l[0], v1l[1]);
        mma_bf16(o[2], al, v1h[0], v1h[1]);
        mma_bf16(o[3], ah, v1h[2], v1h[3]);
        mma_bf16(o[3], ah, v1l[2], v1l[3]);
        mma_bf16(o[3], al, v1h[2], v1h[3]);
    }

    // ---- write O as bf16 hi/lo pair (proj consumes directly) ----
    size_t rowbase = ((size_t)b * NW + w) * NTOK;
#pragma unroll
    for (int t = 0; t < 4; t++) {
        int d = t * 8 + 2 * la3;
        size_t i0 = ((rowbase + r0 + g) * CH + h * DH + d) >> 1;
        size_t i1 = ((rowbase + r0 + g + 8) * CH + h * DH + d) >> 1;
        float e00 = o[t][0] * inv0, e01 = o[t][1] * inv0;
        float e10 = o[t][2] * inv1, e11 = o[t][3] * inv1;
        ((uint32_t*)g_oh)[i0] = pack_hi(e00, e01);
        ((uint32_t*)g_ol)[i0] = pack_lo(e00, e01);
        ((uint32_t*)g_oh)[i1] = pack_hi(e10, e11);
        ((uint32_t*)g_ol)[i1] = pack_lo(e10, e11);
    }
}

// ---------------------------------------------------------------------------
extern "C" void kernel_launch(void* const* d_in, const int* in_sizes, int n_in,
                              void* d_out, int out_size)
{
    const float* x          = (const float*)d_in[0];
    const float* mask       = (const float*)d_in[1];
    const float* w_qkv      = (const float*)d_in[2];
    const float* b_qkv      = (const float*)d_in[3];
    const float* w_proj     = (const float*)d_in[4];
    const float* b_proj     = (const float*)d_in[5];
    const float* bias_table = (const float*)d_in[6];
    const int*   pidx       = (const int*)d_in[7];
    float* out = (float*)d_out;

    cudaFuncSetAttribute(attn_mma_kernel,
                         cudaFuncAttributeMaxDynamicSharedMemorySize,
                         ATTN_SMEM_BYTES);
    cudaFuncSetAttribute(qkv_gemm_mma,
                         cudaFuncAttributeMaxDynamicSharedMemorySize,
                         GEMM_SMEM_BYTES);
    cudaFuncSetAttribute(proj_gemm_mma,
                         cudaFuncAttributeMaxDynamicSharedMemorySize,
                         GEMM_SMEM_BYTES);

    split_x_kernel<<<2048, 256>>>(x);
    split_w_kernel<<<NQKV + CH, 192>>>(w_qkv, w_proj);
    bias_precompute_kernel<<<NW * HEADS_, 256>>>(bias_table, pidx);
    qkv_gemm_mma<<<dim3(9, 1080), 256, GEMM_SMEM_BYTES>>>(b_qkv);
    attn_mma_kernel<<<dim3(HEADS_, NW, B_), 288, ATTN_SMEM_BYTES>>>(mask);
    proj_gemm_mma<<<dim3(3, 1080), 256, GEMM_SMEM_BYTES>>>(b_proj, out);
}